// round 9
// baseline (speedup 1.0000x reference)
#include <cuda_runtime.h>
#include <math.h>
#include <stdint.h>

// Problem constants
#define BB 32
#define TT 256
#define EE 256
#define HH 512
#define G4 2048          // 4*H
#define VV 32000
#define BT 8192          // B*T

// ---------------------------------------------------------------------------
// Scratch (no allocations allowed -> __device__ globals)
// ---------------------------------------------------------------------------
__device__ int g_idx[BT];
__device__ float g_xg[(size_t)BT * G4];     // [t][b][4H] gate preactivations
__device__ float g_hs[(size_t)BT * HH];     // [t][b][H] hidden states (fp32)
__device__ float g_hs_t[(size_t)BT * HH];   // tf32-rounded copy for GEMMs
__device__ float g_emb_t[(size_t)VV * EE];  // tf32-rounded embed_w
__device__ float g_wih_t[(size_t)G4 * EE];  // tf32-rounded w_ih
__device__ float g_fcw_t[(size_t)VV * HH];  // tf32-rounded fc_w
__device__ float g_lnw_t[(size_t)HH * HH];  // tf32-rounded ln_w
__device__ unsigned g_bar_count = 0;
__device__ volatile unsigned g_bar_gen = 0;

// ---------------------------------------------------------------------------
// Small helpers
// ---------------------------------------------------------------------------
__device__ __forceinline__ uint32_t f2tf32(float f) {
    uint32_t r;
    asm("cvt.rna.tf32.f32 %0, %1;" : "=r"(r) : "f"(f));
    return r;
}
__device__ __forceinline__ unsigned long long pk2(float x, float y) {
    unsigned long long r;
    asm("mov.b64 %0, {%1, %2};" : "=l"(r) : "f"(x), "f"(y));
    return r;
}
__device__ __forceinline__ void upk2(unsigned long long v, float& x, float& y) {
    asm("mov.b64 {%0, %1}, %2;" : "=f"(x), "=f"(y) : "l"(v));
}
__device__ __forceinline__ void fma2(unsigned long long& d, unsigned long long a,
                                     unsigned long long b) {
    asm("fma.rn.f32x2 %0, %1, %2, %3;" : "=l"(d) : "l"(a), "l"(b), "l"(d));
}
__device__ __forceinline__ uint32_t smem_u32(const void* p) {
    uint32_t a;
    asm("{ .reg .u64 t; cvta.to.shared.u64 t, %1; cvt.u32.u64 %0, t; }"
        : "=r"(a) : "l"(p));
    return a;
}
__device__ __forceinline__ void cp16(uint32_t dst, const void* src) {
    asm volatile("cp.async.cg.shared.global [%0], [%1], 16;"
                 :: "r"(dst), "l"(src) : "memory");
}
#define CP_COMMIT() asm volatile("cp.async.commit_group;" ::: "memory")
#define CP_WAIT1()  asm volatile("cp.async.wait_group 1;" ::: "memory")
#define CP_WAIT0()  asm volatile("cp.async.wait_group 0;" ::: "memory")

__device__ __forceinline__ void mma_tf32(float* c, const uint32_t* a,
                                         const uint32_t* b) {
    asm volatile(
        "mma.sync.aligned.m16n8k8.row.col.f32.tf32.tf32.f32 "
        "{%0,%1,%2,%3}, {%4,%5,%6,%7}, {%8,%9}, {%0,%1,%2,%3};"
        : "+f"(c[0]), "+f"(c[1]), "+f"(c[2]), "+f"(c[3])
        : "r"(a[0]), "r"(a[1]), "r"(a[2]), "r"(a[3]), "r"(b[0]), "r"(b[1]));
}

// ---------------------------------------------------------------------------
// Token index decode: handles both int64 and int32 storage of x
// ---------------------------------------------------------------------------
__global__ void decode_idx_kernel(const void* __restrict__ xin) {
    int i = blockIdx.x * blockDim.x + threadIdx.x;
    if (i >= BT) return;
    const long long* x64 = (const long long*)xin;
    bool is64 = true;
#pragma unroll
    for (int j = 0; j < 8; j++) {
        long long v = x64[j];
        if (v < 0 || v >= VV) is64 = false;
    }
    g_idx[i] = is64 ? (int)x64[i] : ((const int*)xin)[i];
}

// ---------------------------------------------------------------------------
// Pre-round fp32 -> tf32 bit patterns (RNA), float4 grid-stride.
// ---------------------------------------------------------------------------
__global__ void cvt_tf32_kernel(float* __restrict__ dst,
                                const float* __restrict__ src, int n4) {
    int i = blockIdx.x * blockDim.x + threadIdx.x;
    if (i >= n4) return;
    float4 v = ((const float4*)src)[i];
    uint4 o = make_uint4(f2tf32(v.x), f2tf32(v.y), f2tf32(v.z), f2tf32(v.w));
    ((uint4*)dst)[i] = o;
}

// ---------------------------------------------------------------------------
// mma.sync tf32 GEMM, cp.async staging, 128 threads, CTA 128x128, BK=32.
// 4 warps (2M x 2N), warp tile 64x64, m16n8k8 fragments from padded
// row-major smem (stride 36 words) via conflict-free LDS.32.
// Inputs are pre-rounded tf32 bit patterns -> no cvt in the hot loop.
//   MODE 0: fc  (A=g_hs_t remap, K=512, out row-major stride VV)
//   MODE 1: ln  (A=g_hs_t remap, K=512, out row-major stride HH)
//   MODE 2: xg  (A=g_emb_t gathered via g_idx, K=256, out -> g_xg remap)
// ---------------------------------------------------------------------------
#define MMS 36
#define TILE_W (128 * MMS)        // 4608 words
#define BUF_W (2 * TILE_W)        // 9216 words
#define MM_SMEM_BYTES (2 * BUF_W * 4)   // 73728

template <int KITERS, int MODE>
__global__ __launch_bounds__(128, 2) void gemm_mma2(
    const float* __restrict__ Wt,    // [N][K] tf32 bits
    const float* __restrict__ bias,  // [N]
    float* __restrict__ outp)
{
    extern __shared__ uint32_t smem[];
    const uint32_t sbase = smem_u32(smem);
    const int tid = threadIdx.x;
    const int w = tid >> 5;
    const int lane = tid & 31;
    const int g = lane >> 2;
    const int t = lane & 3;
    const int wm = w >> 1;     // 0..1
    const int wn = w & 1;      // 0..1
    const int by = blockIdx.y;
    const int m0 = by * 128;
    const int n0 = blockIdx.x * 128;
    constexpr int K = KITERS * 32;

    // Per-thread A row pointer (row = tid within tile)
    const float* aRow;
    if (MODE == 2) {
        aRow = g_emb_t + (size_t)g_idx[m0 + tid] * EE;
    } else {
        aRow = g_hs_t + ((size_t)((by & 1) * 128 + tid) * 32 + (by >> 1)) * HH;
    }
    const float* bRow = Wt + (size_t)(n0 + tid) * K;
    const uint32_t stgA = sbase + tid * 144;   // 36 words * 4B

    float c[4][8][4];
#pragma unroll
    for (int mi = 0; mi < 4; mi++)
#pragma unroll
        for (int ni = 0; ni < 8; ni++)
#pragma unroll
            for (int q = 0; q < 4; q++) c[mi][ni][q] = 0.f;

    auto ISSUE = [&](int s) {
        const uint32_t aD = stgA + (s & 1) * (BUF_W * 4);
        const uint32_t bD = aD + TILE_W * 4;
        const float* as = aRow + s * 32;
        const float* bs = bRow + s * 32;
#pragma unroll
        for (int cch = 0; cch < 8; cch++) {
            cp16(aD + cch * 16, as + cch * 4);
            cp16(bD + cch * 16, bs + cch * 4);
        }
        CP_COMMIT();
    };

    ISSUE(0);
    for (int s = 0; s < KITERS; s++) {
        if (s + 1 < KITERS) { ISSUE(s + 1); CP_WAIT1(); }
        else                { CP_WAIT0(); }
        __syncthreads();

        const uint32_t* aC = smem + (s & 1) * BUF_W + (wm * 64 + g) * MMS + t;
        const uint32_t* bC = smem + (s & 1) * BUF_W + TILE_W +
                             (wn * 64 + g) * MMS + t;
#pragma unroll
        for (int kk = 0; kk < 4; kk++) {
            uint32_t af[4][4];
#pragma unroll
            for (int mi = 0; mi < 4; mi++) {
                const uint32_t* p = aC + mi * (16 * MMS) + kk * 8;
                af[mi][0] = p[0];
                af[mi][1] = p[8 * MMS];
                af[mi][2] = p[4];
                af[mi][3] = p[8 * MMS + 4];
            }
            uint32_t bf[8][2];
#pragma unroll
            for (int ni = 0; ni < 8; ni++) {
                const uint32_t* p = bC + ni * (8 * MMS) + kk * 8;
                bf[ni][0] = p[0];
                bf[ni][1] = p[4];
            }
#pragma unroll
            for (int mi = 0; mi < 4; mi++)
#pragma unroll
                for (int ni = 0; ni < 8; ni++)
                    mma_tf32(c[mi][ni], af[mi], bf[ni]);
        }
        __syncthreads();
    }

    // Epilogue
    const int col0 = n0 + wn * 64 + 2 * t;
    float2 bias2[8];
#pragma unroll
    for (int ni = 0; ni < 8; ni++)
        bias2[ni] = *(const float2*)(bias + col0 + ni * 8);
#pragma unroll
    for (int mi = 0; mi < 4; mi++) {
        int gm = m0 + wm * 64 + mi * 16 + g;
        float *r0, *r1;
        if (MODE == 0) {
            r0 = outp + (size_t)gm * VV;
            r1 = outp + (size_t)(gm + 8) * VV;
        } else if (MODE == 1) {
            r0 = outp + (size_t)gm * HH;
            r1 = outp + (size_t)(gm + 8) * HH;
        } else {
            r0 = g_xg + (size_t)((gm & 255) * 32 + (gm >> 8)) * G4;
            int gm8 = gm + 8;
            r1 = g_xg + (size_t)((gm8 & 255) * 32 + (gm8 >> 8)) * G4;
        }
#pragma unroll
        for (int ni = 0; ni < 8; ni++) {
            float2 v0 = make_float2(c[mi][ni][0] + bias2[ni].x,
                                    c[mi][ni][1] + bias2[ni].y);
            float2 v1 = make_float2(c[mi][ni][2] + bias2[ni].x,
                                    c[mi][ni][3] + bias2[ni].y);
            *(float2*)(r0 + col0 + ni * 8) = v0;
            *(float2*)(r1 + col0 + ni * 8) = v1;
        }
    }
}

// ---------------------------------------------------------------------------
// Persistent LSTM kernel: 128 blocks x 256 threads, 1/SM.
// Thread layout: ks = tid&15 (k-slices, stride 16), rg = (tid>>4)&3
// (4 gate-rows each), bg = tid>>6 (8 batches each).
// h replication 4x (was 8x); FFMA2 over batch pairs; transposed k-slice
// reduction buffer (stride 513) kills the 32-way reduce bank conflict.
// ---------------------------------------------------------------------------
#define LSTM_BLOCKS 128
#define LSTM_SMEM_FLOATS (32 * 512 + 16 * 513 + 512 + 128 + 16)
#define LSTM_SMEM_BYTES (LSTM_SMEM_FLOATS * 4)   // 100992

__device__ __forceinline__ int lstm_grow(int j0, int r) {
    return (r >> 2) * 512 + j0 + (r & 3);   // gate g = r>>2, unit u = r&3
}

__device__ __forceinline__ void grid_barrier() {
    __threadfence();
    __syncthreads();
    if (threadIdx.x == 0) {
        unsigned gen = g_bar_gen;
        unsigned arr = atomicAdd(&g_bar_count, 1u);
        if (arr == gridDim.x - 1) {
            g_bar_count = 0;
            __threadfence();
            g_bar_gen = gen + 1;
        } else {
            while (g_bar_gen == gen) { }
        }
    }
    __syncthreads();
    __threadfence();
}

__global__ __launch_bounds__(256) void lstm_kernel(const float* __restrict__ w_hh,
                                                   const float* __restrict__ b_hh) {
    extern __shared__ float sm[];
    float* sH    = sm;                       // [32][512]
    float* sRedT = sH + 32 * 512;            // [16 ks][513] (512 outputs + pad)
    float* sGate = sRedT + 16 * 513;         // [16 rows][32 b]
    float* sC    = sGate + 512;              // [4 units][32 b]
    float* sBh   = sC + 128;                 // [16]

    const int tid = threadIdx.x;
    const int bid = blockIdx.x;
    const int j0 = bid * 4;
    const int ks = tid & 15;
    const int rg = (tid >> 4) & 3;
    const int bg = tid >> 6;

    // Register-resident weight fragments: 4 rows x 32 k-values
    float wv[4][32];
#pragma unroll
    for (int j = 0; j < 4; j++) {
        const float* p = w_hh + (size_t)lstm_grow(j0, rg * 4 + j) * 512 + ks;
#pragma unroll
        for (int i = 0; i < 32; i++) wv[j][i] = p[i * 16];
    }
    if (tid < 16) sBh[tid] = b_hh[lstm_grow(j0, tid)];
    if (tid < 128) sC[tid] = 0.f;
    for (int i = tid; i < 32 * 512; i += 256) sH[i] = 0.f;   // h(-1) = 0
    __syncthreads();

    for (int t = 0; t < TT; t++) {
        if (t > 0) {
            const float4* src = (const float4*)(g_hs + (size_t)(t - 1) * 32 * 512);
            float4* dst = (float4*)sH;
#pragma unroll
            for (int i = 0; i < 16; i++) dst[tid + 256 * i] = src[tid + 256 * i];
            __syncthreads();
        }

        // Partial dots: 4 rows x 8 batches x 32 k per thread, FFMA2 on b-pairs
        unsigned long long acc2[4][4];
#pragma unroll
        for (int j = 0; j < 4; j++)
#pragma unroll
            for (int p = 0; p < 4; p++) acc2[j][p] = 0ull;

        const float* hB = sH + bg * 8 * 512;
#pragma unroll
        for (int i = 0; i < 32; i++) {
            const float* hp = hB + ks + 16 * i;
            unsigned long long hp2[4];
#pragma unroll
            for (int p = 0; p < 4; p++)
                hp2[p] = pk2(hp[(2 * p) * 512], hp[(2 * p + 1) * 512]);
#pragma unroll
            for (int j = 0; j < 4; j++) {
                unsigned long long w2 = pk2(wv[j][i], wv[j][i]);
#pragma unroll
                for (int p = 0; p < 4; p++) fma2(acc2[j][p], w2, hp2[p]);
            }
        }
#pragma unroll
        for (int j = 0; j < 4; j++) {
            int r = rg * 4 + j;
#pragma unroll
            for (int p = 0; p < 4; p++) {
                float a0, a1;
                upk2(acc2[j][p], a0, a1);
                int o = r * 32 + bg * 8 + 2 * p;
                sRedT[ks * 513 + o]     = a0;
                sRedT[ks * 513 + o + 1] = a1;
            }
        }
        __syncthreads();

        // Reduce 16 k-slices, add xg + b_hh
#pragma unroll
        for (int o2 = 0; o2 < 2; o2++) {
            int o = tid * 2 + o2;
            int r = o >> 5, b = o & 31;
            float s = 0.f;
#pragma unroll
            for (int j = 0; j < 16; j++) s += sRedT[j * 513 + o];
            s += g_xg[(size_t)(t * 32 + b) * G4 + lstm_grow(j0, r)] + sBh[r];
            sGate[o] = s;
        }
        __syncthreads();

        // Activations + state update (gate order i,f,g,o)
        if (tid < 128) {
            int u = tid & 3, b = tid >> 2;
            float gi = sGate[(0 + u) * 32 + b];
            float gf = sGate[(4 + u) * 32 + b];
            float gg = sGate[(8 + u) * 32 + b];
            float go = sGate[(12 + u) * 32 + b];
            float cc = sC[u * 32 + b];
            float si = 1.f / (1.f + expf(-gi));
            float sf = 1.f / (1.f + expf(-gf));
            float so = 1.f / (1.f + expf(-go));
            cc = sf * cc + si * tanhf(gg);
            float h = so * tanhf(cc);
            sC[u * 32 + b] = cc;
            size_t off = (size_t)(t * 32 + b) * 512 + j0 + u;
            g_hs[off] = h;
            g_hs_t[off] = __uint_as_float(f2tf32(h));
        }
        grid_barrier();
    }
}

// ---------------------------------------------------------------------------
// Launch
// ---------------------------------------------------------------------------
extern "C" void kernel_launch(void* const* d_in, const int* in_sizes, int n_in,
                              void* d_out, int out_size) {
    const void*  x       = d_in[0];
    const float* embed_w = (const float*)d_in[1];
    const float* w_ih    = (const float*)d_in[2];
    const float* w_hh    = (const float*)d_in[3];
    const float* b_ih    = (const float*)d_in[4];
    const float* b_hh    = (const float*)d_in[5];
    const float* fc_w    = (const float*)d_in[6];
    const float* fc_b    = (const float*)d_in[7];
    const float* ln_w    = (const float*)d_in[8];
    const float* ln_b    = (const float*)d_in[9];

    float* out    = (float*)d_out;
    float* states = out + (size_t)BT * VV;

    // Resolve device scratch addresses
    float *emb_t, *wih_t, *fcw_t, *lnw_t;
    cudaGetSymbolAddress((void**)&emb_t, g_emb_t);
    cudaGetSymbolAddress((void**)&wih_t, g_wih_t);
    cudaGetSymbolAddress((void**)&fcw_t, g_fcw_t);
    cudaGetSymbolAddress((void**)&lnw_t, g_lnw_t);

    // 1) decode token indices
    decode_idx_kernel<<<BT / 256, 256>>>(x);

    // 2) pre-round weights to tf32 (RNA)
    cvt_tf32_kernel<<<(VV * EE / 4) / 256, 256>>>(emb_t, embed_w, VV * EE / 4);
    cvt_tf32_kernel<<<(G4 * EE / 4) / 256, 256>>>(wih_t, w_ih, G4 * EE / 4);
    cvt_tf32_kernel<<<(VV * HH / 4) / 256, 256>>>(fcw_t, fc_w, VV * HH / 4);
    cvt_tf32_kernel<<<(HH * HH / 4) / 256, 256>>>(lnw_t, ln_w, HH * HH / 4);

    // 3) xg = embed[x] @ w_ih^T + b_ih   (tensor tf32, K=256)
    cudaFuncSetAttribute(gemm_mma2<8, 2>,
                         cudaFuncAttributeMaxDynamicSharedMemorySize, MM_SMEM_BYTES);
    gemm_mma2<8, 2><<<dim3(G4 / 128, BT / 128), 128, MM_SMEM_BYTES>>>(
        wih_t, b_ih, nullptr);

    // 4) sequential LSTM (fp32 recurrence; emits fp32 + tf32 hs)
    cudaFuncSetAttribute(lstm_kernel, cudaFuncAttributeMaxDynamicSharedMemorySize,
                         LSTM_SMEM_BYTES);
    lstm_kernel<<<LSTM_BLOCKS, 256, LSTM_SMEM_BYTES>>>(w_hh, b_hh);

    // 5) out = hs @ fc_w^T + fc_b   (tensor tf32, K=512)
    cudaFuncSetAttribute(gemm_mma2<16, 0>,
                         cudaFuncAttributeMaxDynamicSharedMemorySize, MM_SMEM_BYTES);
    gemm_mma2<16, 0><<<dim3(VV / 128, BT / 128), 128, MM_SMEM_BYTES>>>(
        fcw_t, fc_b, out);

    // 6) states = hs @ ln_w^T + ln_b   (tensor tf32, K=512)
    cudaFuncSetAttribute(gemm_mma2<16, 1>,
                         cudaFuncAttributeMaxDynamicSharedMemorySize, MM_SMEM_BYTES);
    gemm_mma2<16, 1><<<dim3(HH / 128, BT / 128), 128, MM_SMEM_BYTES>>>(
        lnw_t, ln_b, states);
}

// round 10
// speedup vs baseline: 1.3406x; 1.3406x over previous
#include <cuda_runtime.h>
#include <math.h>
#include <stdint.h>

// Problem constants
#define BB 32
#define TT 256
#define EE 256
#define HH 512
#define G4 2048          // 4*H
#define VV 32000
#define BT 8192          // B*T

// ---------------------------------------------------------------------------
// Scratch (no allocations allowed -> __device__ globals)
// ---------------------------------------------------------------------------
__device__ int g_idx[BT];
__device__ float g_xg[(size_t)BT * G4];     // [t][b][4H] gate preactivations
__device__ float g_hs[(size_t)BT * HH];     // [t][b][H] hidden states (fp32)
__device__ float g_hs_t[(size_t)BT * HH];   // tf32-rounded copy for GEMMs
__device__ float g_emb_t[(size_t)VV * EE];  // tf32-rounded embed_w
__device__ float g_wih_t[(size_t)G4 * EE];  // tf32-rounded w_ih
__device__ float g_fcw_t[(size_t)VV * HH];  // tf32-rounded fc_w
__device__ float g_lnw_t[(size_t)HH * HH];  // tf32-rounded ln_w
__device__ unsigned g_bar_count = 0;
__device__ volatile unsigned g_bar_gen = 0;

// ---------------------------------------------------------------------------
// Small helpers
// ---------------------------------------------------------------------------
__device__ __forceinline__ uint32_t f2tf32(float f) {
    uint32_t r;
    asm("cvt.rna.tf32.f32 %0, %1;" : "=r"(r) : "f"(f));
    return r;
}
__device__ __forceinline__ unsigned long long pk2(float x, float y) {
    unsigned long long r;
    asm("mov.b64 %0, {%1, %2};" : "=l"(r) : "f"(x), "f"(y));
    return r;
}
__device__ __forceinline__ void upk2(unsigned long long v, float& x, float& y) {
    asm("mov.b64 {%0, %1}, %2;" : "=f"(x), "=f"(y) : "l"(v));
}
__device__ __forceinline__ void fma2(unsigned long long& d, unsigned long long a,
                                     unsigned long long b) {
    asm("fma.rn.f32x2 %0, %1, %2, %3;" : "=l"(d) : "l"(a), "l"(b), "l"(d));
}
__device__ __forceinline__ uint32_t smem_u32(const void* p) {
    uint32_t a;
    asm("{ .reg .u64 t; cvta.to.shared.u64 t, %1; cvt.u32.u64 %0, t; }"
        : "=r"(a) : "l"(p));
    return a;
}
__device__ __forceinline__ void cp16(uint32_t dst, const void* src) {
    asm volatile("cp.async.cg.shared.global [%0], [%1], 16;"
                 :: "r"(dst), "l"(src) : "memory");
}
#define CP_COMMIT() asm volatile("cp.async.commit_group;" ::: "memory")
#define CP_WAIT1()  asm volatile("cp.async.wait_group 1;" ::: "memory")
#define CP_WAIT0()  asm volatile("cp.async.wait_group 0;" ::: "memory")

__device__ __forceinline__ void mma_tf32(float* c, const uint32_t* a,
                                         const uint32_t* b) {
    asm volatile(
        "mma.sync.aligned.m16n8k8.row.col.f32.tf32.tf32.f32 "
        "{%0,%1,%2,%3}, {%4,%5,%6,%7}, {%8,%9}, {%0,%1,%2,%3};"
        : "+f"(c[0]), "+f"(c[1]), "+f"(c[2]), "+f"(c[3])
        : "r"(a[0]), "r"(a[1]), "r"(a[2]), "r"(a[3]), "r"(b[0]), "r"(b[1]));
}

// ---------------------------------------------------------------------------
// Token index decode: handles both int64 and int32 storage of x
// ---------------------------------------------------------------------------
__global__ void decode_idx_kernel(const void* __restrict__ xin) {
    int i = blockIdx.x * blockDim.x + threadIdx.x;
    if (i >= BT) return;
    const long long* x64 = (const long long*)xin;
    bool is64 = true;
#pragma unroll
    for (int j = 0; j < 8; j++) {
        long long v = x64[j];
        if (v < 0 || v >= VV) is64 = false;
    }
    g_idx[i] = is64 ? (int)x64[i] : ((const int*)xin)[i];
}

// ---------------------------------------------------------------------------
// Pre-round fp32 -> tf32 bit patterns (RNA), float4 per thread.
// ---------------------------------------------------------------------------
__global__ void cvt_tf32_kernel(float* __restrict__ dst,
                                const float* __restrict__ src, int n4) {
    int i = blockIdx.x * blockDim.x + threadIdx.x;
    if (i >= n4) return;
    float4 v = ((const float4*)src)[i];
    uint4 o = make_uint4(f2tf32(v.x), f2tf32(v.y), f2tf32(v.z), f2tf32(v.w));
    ((uint4*)dst)[i] = o;
}

// ---------------------------------------------------------------------------
// mma.sync tf32 GEMM — R8-proven tiling + cp.async staging:
// CTA 128x128, BK=32, 256 threads, 8 warps (2M x 4N), warp tile 64x32.
// Inputs pre-rounded tf32 bits; cp.async.cg 16B straight into padded
// row-major smem (stride 36 words) -> no STS, no cvt in hot loop.
// Consumer: conflict-free LDS.32 (bank = g*4 + t + C, all lanes distinct).
//   MODE 0: fc  (A=g_hs_t remap, out stride VV)
//   MODE 1: ln  (A=g_hs_t remap, out stride HH)
//   MODE 2: xg  (A=g_emb_t gathered via g_idx, out -> g_xg remap)
// ---------------------------------------------------------------------------
#define MMS 36
#define TILE_W (128 * MMS)        // 4608 words
#define BUF_W (2 * TILE_W)        // 9216 words
#define MM_SMEM_BYTES (2 * BUF_W * 4)   // 73728

template <int KITERS, int MODE>
__global__ __launch_bounds__(256, 2) void gemm_mma3(
    const float* __restrict__ Wt,    // [N][K] tf32 bits
    const float* __restrict__ bias,  // [N]
    float* __restrict__ outp)
{
    extern __shared__ uint32_t smem[];
    const uint32_t sbase = smem_u32(smem);
    const int tid = threadIdx.x;
    const int w = tid >> 5;
    const int lane = tid & 31;
    const int g = lane >> 2;
    const int t = lane & 3;
    const int wm = w >> 2;     // 0..1
    const int wn = w & 3;      // 0..3
    const int by = blockIdx.y;
    const int m0 = by * 128;
    const int n0 = blockIdx.x * 128;
    constexpr int K = KITERS * 32;

    // Staging: thread covers rows (tid>>3)+q*32, 16B chunk (tid&7)
    const int srow = tid >> 3;
    const int schk = (tid & 7) * 4;   // float offset within the 32-col slice
    const float* aP[4];
    const float* bP[4];
#pragma unroll
    for (int q = 0; q < 4; q++) {
        const int r = srow + q * 32;
        if (MODE == 2) {
            aP[q] = g_emb_t + (size_t)g_idx[m0 + r] * EE + schk;
        } else {
            aP[q] = g_hs_t +
                    ((size_t)((by & 1) * 128 + r) * 32 + (size_t)(by >> 1)) * HH +
                    schk;
        }
        bP[q] = Wt + (size_t)(n0 + r) * K + schk;
    }
    const uint32_t stg = sbase + (uint32_t)srow * 144 + (uint32_t)schk * 4;

    float c[4][4][4];
#pragma unroll
    for (int mi = 0; mi < 4; mi++)
#pragma unroll
        for (int ni = 0; ni < 4; ni++)
#pragma unroll
            for (int q = 0; q < 4; q++) c[mi][ni][q] = 0.f;

    auto ISSUE = [&](int s) {
        const uint32_t aD = stg + (s & 1) * (BUF_W * 4);
        const uint32_t bD = aD + TILE_W * 4;
        const int k0 = s * 32;
#pragma unroll
        for (int q = 0; q < 4; q++) {
            cp16(aD + q * (32 * 144), aP[q] + k0);
            cp16(bD + q * (32 * 144), bP[q] + k0);
        }
        CP_COMMIT();
    };

    ISSUE(0);
    for (int s = 0; s < KITERS; s++) {
        if (s + 1 < KITERS) { ISSUE(s + 1); CP_WAIT1(); }
        else                { CP_WAIT0(); }
        __syncthreads();

        const uint32_t* aC = smem + (s & 1) * BUF_W + (wm * 64 + g) * MMS + t;
        const uint32_t* bC = smem + (s & 1) * BUF_W + TILE_W +
                             (wn * 32 + g) * MMS + t;
#pragma unroll
        for (int kk = 0; kk < 4; kk++) {
            uint32_t af[4][4];
#pragma unroll
            for (int mi = 0; mi < 4; mi++) {
                const uint32_t* p = aC + mi * (16 * MMS) + kk * 8;
                af[mi][0] = p[0];
                af[mi][1] = p[8 * MMS];
                af[mi][2] = p[4];
                af[mi][3] = p[8 * MMS + 4];
            }
            uint32_t bf[4][2];
#pragma unroll
            for (int ni = 0; ni < 4; ni++) {
                const uint32_t* p = bC + ni * (8 * MMS) + kk * 8;
                bf[ni][0] = p[0];
                bf[ni][1] = p[4];
            }
#pragma unroll
            for (int mi = 0; mi < 4; mi++)
#pragma unroll
                for (int ni = 0; ni < 4; ni++)
                    mma_tf32(c[mi][ni], af[mi], bf[ni]);
        }
        __syncthreads();
    }

    // Epilogue: direct STG.64 with bias
    const int col0 = n0 + wn * 32 + 2 * t;
    float2 bias2[4];
#pragma unroll
    for (int ni = 0; ni < 4; ni++)
        bias2[ni] = *(const float2*)(bias + col0 + ni * 8);
#pragma unroll
    for (int mi = 0; mi < 4; mi++) {
        int gm = m0 + wm * 64 + mi * 16 + g;
        float *r0, *r1;
        if (MODE == 0) {
            r0 = outp + (size_t)gm * VV;
            r1 = outp + (size_t)(gm + 8) * VV;
        } else if (MODE == 1) {
            r0 = outp + (size_t)gm * HH;
            r1 = outp + (size_t)(gm + 8) * HH;
        } else {
            r0 = g_xg + (size_t)((gm & 255) * 32 + (gm >> 8)) * G4;
            int gm8 = gm + 8;
            r1 = g_xg + (size_t)((gm8 & 255) * 32 + (gm8 >> 8)) * G4;
        }
#pragma unroll
        for (int ni = 0; ni < 4; ni++) {
            float2 v0 = make_float2(c[mi][ni][0] + bias2[ni].x,
                                    c[mi][ni][1] + bias2[ni].y);
            float2 v1 = make_float2(c[mi][ni][2] + bias2[ni].x,
                                    c[mi][ni][3] + bias2[ni].y);
            *(float2*)(r0 + col0 + ni * 8) = v0;
            *(float2*)(r1 + col0 + ni * 8) = v1;
        }
    }
}

// ---------------------------------------------------------------------------
// Persistent LSTM kernel (R9 version: FFMA2 + conflict-free reduce).
// 128 blocks x 256 threads, 1/SM. ks = tid&15, rg = (tid>>4)&3, bg = tid>>6.
// ---------------------------------------------------------------------------
#define LSTM_BLOCKS 128
#define LSTM_SMEM_FLOATS (32 * 512 + 16 * 513 + 512 + 128 + 16)
#define LSTM_SMEM_BYTES (LSTM_SMEM_FLOATS * 4)   // 100992

__device__ __forceinline__ int lstm_grow(int j0, int r) {
    return (r >> 2) * 512 + j0 + (r & 3);   // gate g = r>>2, unit u = r&3
}

__device__ __forceinline__ void grid_barrier() {
    __threadfence();
    __syncthreads();
    if (threadIdx.x == 0) {
        unsigned gen = g_bar_gen;
        unsigned arr = atomicAdd(&g_bar_count, 1u);
        if (arr == gridDim.x - 1) {
            g_bar_count = 0;
            __threadfence();
            g_bar_gen = gen + 1;
        } else {
            while (g_bar_gen == gen) { }
        }
    }
    __syncthreads();
    __threadfence();
}

__global__ __launch_bounds__(256) void lstm_kernel(const float* __restrict__ w_hh,
                                                   const float* __restrict__ b_hh) {
    extern __shared__ float sm[];
    float* sH    = sm;                       // [32][512]
    float* sRedT = sH + 32 * 512;            // [16 ks][513]
    float* sGate = sRedT + 16 * 513;         // [16 rows][32 b]
    float* sC    = sGate + 512;              // [4 units][32 b]
    float* sBh   = sC + 128;                 // [16]

    const int tid = threadIdx.x;
    const int bid = blockIdx.x;
    const int j0 = bid * 4;
    const int ks = tid & 15;
    const int rg = (tid >> 4) & 3;
    const int bg = tid >> 6;

    float wv[4][32];
#pragma unroll
    for (int j = 0; j < 4; j++) {
        const float* p = w_hh + (size_t)lstm_grow(j0, rg * 4 + j) * 512 + ks;
#pragma unroll
        for (int i = 0; i < 32; i++) wv[j][i] = p[i * 16];
    }
    if (tid < 16) sBh[tid] = b_hh[lstm_grow(j0, tid)];
    if (tid < 128) sC[tid] = 0.f;
    for (int i = tid; i < 32 * 512; i += 256) sH[i] = 0.f;
    __syncthreads();

    for (int t = 0; t < TT; t++) {
        if (t > 0) {
            const float4* src = (const float4*)(g_hs + (size_t)(t - 1) * 32 * 512);
            float4* dst = (float4*)sH;
#pragma unroll
            for (int i = 0; i < 16; i++) dst[tid + 256 * i] = src[tid + 256 * i];
            __syncthreads();
        }

        unsigned long long acc2[4][4];
#pragma unroll
        for (int j = 0; j < 4; j++)
#pragma unroll
            for (int p = 0; p < 4; p++) acc2[j][p] = 0ull;

        const float* hB = sH + bg * 8 * 512;
#pragma unroll
        for (int i = 0; i < 32; i++) {
            const float* hp = hB + ks + 16 * i;
            unsigned long long hp2[4];
#pragma unroll
            for (int p = 0; p < 4; p++)
                hp2[p] = pk2(hp[(2 * p) * 512], hp[(2 * p + 1) * 512]);
#pragma unroll
            for (int j = 0; j < 4; j++) {
                unsigned long long w2 = pk2(wv[j][i], wv[j][i]);
#pragma unroll
                for (int p = 0; p < 4; p++) fma2(acc2[j][p], w2, hp2[p]);
            }
        }
#pragma unroll
        for (int j = 0; j < 4; j++) {
            int r = rg * 4 + j;
#pragma unroll
            for (int p = 0; p < 4; p++) {
                float a0, a1;
                upk2(acc2[j][p], a0, a1);
                int o = r * 32 + bg * 8 + 2 * p;
                sRedT[ks * 513 + o]     = a0;
                sRedT[ks * 513 + o + 1] = a1;
            }
        }
        __syncthreads();

#pragma unroll
        for (int o2 = 0; o2 < 2; o2++) {
            int o = tid * 2 + o2;
            int r = o >> 5, b = o & 31;
            float s = 0.f;
#pragma unroll
            for (int j = 0; j < 16; j++) s += sRedT[j * 513 + o];
            s += g_xg[(size_t)(t * 32 + b) * G4 + lstm_grow(j0, r)] + sBh[r];
            sGate[o] = s;
        }
        __syncthreads();

        if (tid < 128) {
            int u = tid & 3, b = tid >> 2;
            float gi = sGate[(0 + u) * 32 + b];
            float gf = sGate[(4 + u) * 32 + b];
            float gg = sGate[(8 + u) * 32 + b];
            float go = sGate[(12 + u) * 32 + b];
            float cc = sC[u * 32 + b];
            float si = 1.f / (1.f + expf(-gi));
            float sf = 1.f / (1.f + expf(-gf));
            float so = 1.f / (1.f + expf(-go));
            cc = sf * cc + si * tanhf(gg);
            float h = so * tanhf(cc);
            sC[u * 32 + b] = cc;
            size_t off = (size_t)(t * 32 + b) * 512 + j0 + u;
            g_hs[off] = h;
            g_hs_t[off] = __uint_as_float(f2tf32(h));
        }
        grid_barrier();
    }
}

// ---------------------------------------------------------------------------
// Launch
// ---------------------------------------------------------------------------
extern "C" void kernel_launch(void* const* d_in, const int* in_sizes, int n_in,
                              void* d_out, int out_size) {
    const void*  x       = d_in[0];
    const float* embed_w = (const float*)d_in[1];
    const float* w_ih    = (const float*)d_in[2];
    const float* w_hh    = (const float*)d_in[3];
    const float* b_ih    = (const float*)d_in[4];
    const float* b_hh    = (const float*)d_in[5];
    const float* fc_w    = (const float*)d_in[6];
    const float* fc_b    = (const float*)d_in[7];
    const float* ln_w    = (const float*)d_in[8];
    const float* ln_b    = (const float*)d_in[9];

    float* out    = (float*)d_out;
    float* states = out + (size_t)BT * VV;

    float *emb_t, *wih_t, *fcw_t, *lnw_t;
    cudaGetSymbolAddress((void**)&emb_t, g_emb_t);
    cudaGetSymbolAddress((void**)&wih_t, g_wih_t);
    cudaGetSymbolAddress((void**)&fcw_t, g_fcw_t);
    cudaGetSymbolAddress((void**)&lnw_t, g_lnw_t);

    // 1) decode token indices
    decode_idx_kernel<<<BT / 256, 256>>>(x);

    // 2) pre-round weights to tf32 (RNA)
    cvt_tf32_kernel<<<(VV * EE / 4) / 256, 256>>>(emb_t, embed_w, VV * EE / 4);
    cvt_tf32_kernel<<<(G4 * EE / 4) / 256, 256>>>(wih_t, w_ih, G4 * EE / 4);
    cvt_tf32_kernel<<<(VV * HH / 4) / 256, 256>>>(fcw_t, fc_w, VV * HH / 4);
    cvt_tf32_kernel<<<(HH * HH / 4) / 256, 256>>>(lnw_t, ln_w, HH * HH / 4);

    // 3) xg = embed[x] @ w_ih^T + b_ih   (tensor tf32, K=256)
    cudaFuncSetAttribute(gemm_mma3<8, 2>,
                         cudaFuncAttributeMaxDynamicSharedMemorySize, MM_SMEM_BYTES);
    gemm_mma3<8, 2><<<dim3(G4 / 128, BT / 128), 256, MM_SMEM_BYTES>>>(
        wih_t, b_ih, nullptr);

    // 4) sequential LSTM (fp32 recurrence; emits fp32 + tf32 hs)
    cudaFuncSetAttribute(lstm_kernel, cudaFuncAttributeMaxDynamicSharedMemorySize,
                         LSTM_SMEM_BYTES);
    lstm_kernel<<<LSTM_BLOCKS, 256, LSTM_SMEM_BYTES>>>(w_hh, b_hh);

    // 5) out = hs @ fc_w^T + fc_b   (tensor tf32, K=512)
    cudaFuncSetAttribute(gemm_mma3<16, 0>,
                         cudaFuncAttributeMaxDynamicSharedMemorySize, MM_SMEM_BYTES);
    gemm_mma3<16, 0><<<dim3(VV / 128, BT / 128), 256, MM_SMEM_BYTES>>>(
        fcw_t, fc_b, out);

    // 6) states = hs @ ln_w^T + ln_b   (tensor tf32, K=512)
    cudaFuncSetAttribute(gemm_mma3<16, 1>,
                         cudaFuncAttributeMaxDynamicSharedMemorySize, MM_SMEM_BYTES);
    gemm_mma3<16, 1><<<dim3(HH / 128, BT / 128), 256, MM_SMEM_BYTES>>>(
        lnw_t, ln_b, states);
}

// round 11
// speedup vs baseline: 1.6935x; 1.2633x over previous
#include <cuda_runtime.h>
#include <cuda_bf16.h>
#include <math.h>
#include <stdint.h>

// Problem constants
#define BB 32
#define TT 256
#define EE 256
#define HH 512
#define G4 2048          // 4*H
#define VV 32000
#define BT 8192          // B*T

// ---------------------------------------------------------------------------
// Scratch (no allocations allowed -> __device__ globals)
// ---------------------------------------------------------------------------
__device__ int g_idx[BT];
__device__ float g_xg[(size_t)BT * G4];     // [t][b][4H] gate preactivations
__device__ float g_hs[(size_t)BT * HH];     // [t][b][H] hidden states (fp32)
__device__ __nv_bfloat16 g_hs_b[(size_t)BT * HH];   // bf16 copy for fc/ln GEMMs
__device__ float g_emb_t[(size_t)VV * EE];  // tf32-rounded embed_w
__device__ float g_wih_t[(size_t)G4 * EE];  // tf32-rounded w_ih
__device__ __nv_bfloat16 g_fcw_b[(size_t)VV * HH];  // bf16 fc_w
__device__ __nv_bfloat16 g_lnw_b[(size_t)HH * HH];  // bf16 ln_w
__device__ unsigned g_bar_count = 0;
__device__ volatile unsigned g_bar_gen = 0;

// ---------------------------------------------------------------------------
// Small helpers
// ---------------------------------------------------------------------------
__device__ __forceinline__ uint32_t f2tf32(float f) {
    uint32_t r;
    asm("cvt.rna.tf32.f32 %0, %1;" : "=r"(r) : "f"(f));
    return r;
}
__device__ __forceinline__ uint32_t bf2x(float lo, float hi) {
    uint32_t r;
    asm("cvt.rn.bf16x2.f32 %0, %1, %2;" : "=r"(r) : "f"(hi), "f"(lo));
    return r;
}
__device__ __forceinline__ unsigned long long pk2(float x, float y) {
    unsigned long long r;
    asm("mov.b64 %0, {%1, %2};" : "=l"(r) : "f"(x), "f"(y));
    return r;
}
__device__ __forceinline__ void upk2(unsigned long long v, float& x, float& y) {
    asm("mov.b64 {%0, %1}, %2;" : "=f"(x), "=f"(y) : "l"(v));
}
__device__ __forceinline__ void fma2(unsigned long long& d, unsigned long long a,
                                     unsigned long long b) {
    asm("fma.rn.f32x2 %0, %1, %2, %3;" : "=l"(d) : "l"(a), "l"(b), "l"(d));
}
__device__ __forceinline__ uint32_t smem_u32(const void* p) {
    uint32_t a;
    asm("{ .reg .u64 t; cvta.to.shared.u64 t, %1; cvt.u32.u64 %0, t; }"
        : "=r"(a) : "l"(p));
    return a;
}
__device__ __forceinline__ void cp16(uint32_t dst, const void* src) {
    asm volatile("cp.async.cg.shared.global [%0], [%1], 16;"
                 :: "r"(dst), "l"(src) : "memory");
}
#define CP_COMMIT() asm volatile("cp.async.commit_group;" ::: "memory")
#define CP_WAIT1()  asm volatile("cp.async.wait_group 1;" ::: "memory")
#define CP_WAIT0()  asm volatile("cp.async.wait_group 0;" ::: "memory")

__device__ __forceinline__ void mma_tf32(float* c, const uint32_t* a,
                                         const uint32_t* b) {
    asm volatile(
        "mma.sync.aligned.m16n8k8.row.col.f32.tf32.tf32.f32 "
        "{%0,%1,%2,%3}, {%4,%5,%6,%7}, {%8,%9}, {%0,%1,%2,%3};"
        : "+f"(c[0]), "+f"(c[1]), "+f"(c[2]), "+f"(c[3])
        : "r"(a[0]), "r"(a[1]), "r"(a[2]), "r"(a[3]), "r"(b[0]), "r"(b[1]));
}
__device__ __forceinline__ void mma_bf16(float* c, const uint32_t* a,
                                         const uint32_t* b) {
    asm volatile(
        "mma.sync.aligned.m16n8k16.row.col.f32.bf16.bf16.f32 "
        "{%0,%1,%2,%3}, {%4,%5,%6,%7}, {%8,%9}, {%0,%1,%2,%3};"
        : "+f"(c[0]), "+f"(c[1]), "+f"(c[2]), "+f"(c[3])
        : "r"(a[0]), "r"(a[1]), "r"(a[2]), "r"(a[3]), "r"(b[0]), "r"(b[1]));
}

// ---------------------------------------------------------------------------
// Token index decode: handles both int64 and int32 storage of x
// ---------------------------------------------------------------------------
__global__ void decode_idx_kernel(const void* __restrict__ xin) {
    int i = blockIdx.x * blockDim.x + threadIdx.x;
    if (i >= BT) return;
    const long long* x64 = (const long long*)xin;
    bool is64 = true;
#pragma unroll
    for (int j = 0; j < 8; j++) {
        long long v = x64[j];
        if (v < 0 || v >= VV) is64 = false;
    }
    g_idx[i] = is64 ? (int)x64[i] : ((const int*)xin)[i];
}

// ---------------------------------------------------------------------------
// Pre-round fp32 -> tf32 bit patterns (RNA), float4 per thread.
// ---------------------------------------------------------------------------
__global__ void cvt_tf32_kernel(float* __restrict__ dst,
                                const float* __restrict__ src, int n4) {
    int i = blockIdx.x * blockDim.x + threadIdx.x;
    if (i >= n4) return;
    float4 v = ((const float4*)src)[i];
    uint4 o = make_uint4(f2tf32(v.x), f2tf32(v.y), f2tf32(v.z), f2tf32(v.w));
    ((uint4*)dst)[i] = o;
}

// ---------------------------------------------------------------------------
// Convert fp32 -> bf16 (RN), 8 elements per thread, 16B writes.
// ---------------------------------------------------------------------------
__global__ void cvt_bf16_kernel(__nv_bfloat16* __restrict__ dst,
                                const float* __restrict__ src, int n8) {
    int i = blockIdx.x * blockDim.x + threadIdx.x;
    if (i >= n8) return;
    float4 v0 = ((const float4*)src)[2 * i];
    float4 v1 = ((const float4*)src)[2 * i + 1];
    uint4 o = make_uint4(bf2x(v0.x, v0.y), bf2x(v0.z, v0.w),
                         bf2x(v1.x, v1.y), bf2x(v1.z, v1.w));
    ((uint4*)dst)[i] = o;
}

// ---------------------------------------------------------------------------
// tf32 mma GEMM (R10-proven) — now used ONLY for xg (MODE 2 path):
// CTA 128x128, BK=32, 256 threads, 8 warps (2M x 4N), cp.async staging.
// ---------------------------------------------------------------------------
#define MMS 36
#define TILE_W (128 * MMS)
#define BUF_W (2 * TILE_W)
#define MM_SMEM_BYTES (2 * BUF_W * 4)   // 73728

__global__ __launch_bounds__(256, 2) void gemm_xg_mma(
    const float* __restrict__ Wt,    // w_ih tf32 bits [2048][256]
    const float* __restrict__ bias)  // b_ih
{
    constexpr int KITERS = 8;
    constexpr int K = 256;
    extern __shared__ uint32_t smem[];
    const uint32_t sbase = smem_u32(smem);
    const int tid = threadIdx.x;
    const int w = tid >> 5;
    const int lane = tid & 31;
    const int g = lane >> 2;
    const int t = lane & 3;
    const int wm = w >> 2;
    const int wn = w & 3;
    const int m0 = blockIdx.y * 128;
    const int n0 = blockIdx.x * 128;

    const int srow = tid >> 3;
    const int schk = (tid & 7) * 4;
    const float* aP[4];
    const float* bP[4];
#pragma unroll
    for (int q = 0; q < 4; q++) {
        const int r = srow + q * 32;
        aP[q] = g_emb_t + (size_t)g_idx[m0 + r] * EE + schk;
        bP[q] = Wt + (size_t)(n0 + r) * K + schk;
    }
    const uint32_t stg = sbase + (uint32_t)srow * 144 + (uint32_t)schk * 4;

    float c[4][4][4];
#pragma unroll
    for (int mi = 0; mi < 4; mi++)
#pragma unroll
        for (int ni = 0; ni < 4; ni++)
#pragma unroll
            for (int q = 0; q < 4; q++) c[mi][ni][q] = 0.f;

    auto ISSUE = [&](int s) {
        const uint32_t aD = stg + (s & 1) * (BUF_W * 4);
        const uint32_t bD = aD + TILE_W * 4;
        const int k0 = s * 32;
#pragma unroll
        for (int q = 0; q < 4; q++) {
            cp16(aD + q * (32 * 144), aP[q] + k0);
            cp16(bD + q * (32 * 144), bP[q] + k0);
        }
        CP_COMMIT();
    };

    ISSUE(0);
    for (int s = 0; s < KITERS; s++) {
        if (s + 1 < KITERS) { ISSUE(s + 1); CP_WAIT1(); }
        else                { CP_WAIT0(); }
        __syncthreads();

        const uint32_t* aC = smem + (s & 1) * BUF_W + (wm * 64 + g) * MMS + t;
        const uint32_t* bC = smem + (s & 1) * BUF_W + TILE_W +
                             (wn * 32 + g) * MMS + t;
#pragma unroll
        for (int kk = 0; kk < 4; kk++) {
            uint32_t af[4][4];
#pragma unroll
            for (int mi = 0; mi < 4; mi++) {
                const uint32_t* p = aC + mi * (16 * MMS) + kk * 8;
                af[mi][0] = p[0];
                af[mi][1] = p[8 * MMS];
                af[mi][2] = p[4];
                af[mi][3] = p[8 * MMS + 4];
            }
            uint32_t bf[4][2];
#pragma unroll
            for (int ni = 0; ni < 4; ni++) {
                const uint32_t* p = bC + ni * (8 * MMS) + kk * 8;
                bf[ni][0] = p[0];
                bf[ni][1] = p[4];
            }
#pragma unroll
            for (int mi = 0; mi < 4; mi++)
#pragma unroll
                for (int ni = 0; ni < 4; ni++)
                    mma_tf32(c[mi][ni], af[mi], bf[ni]);
        }
        __syncthreads();
    }

    const int col0 = n0 + wn * 32 + 2 * t;
    float2 bias2[4];
#pragma unroll
    for (int ni = 0; ni < 4; ni++)
        bias2[ni] = *(const float2*)(bias + col0 + ni * 8);
#pragma unroll
    for (int mi = 0; mi < 4; mi++) {
        int gm = m0 + wm * 64 + mi * 16 + g;
        int gm8 = gm + 8;
        float* r0 = g_xg + (size_t)((gm & 255) * 32 + (gm >> 8)) * G4;
        float* r1 = g_xg + (size_t)((gm8 & 255) * 32 + (gm8 >> 8)) * G4;
#pragma unroll
        for (int ni = 0; ni < 4; ni++) {
            float2 v0 = make_float2(c[mi][ni][0] + bias2[ni].x,
                                    c[mi][ni][1] + bias2[ni].y);
            float2 v1 = make_float2(c[mi][ni][2] + bias2[ni].x,
                                    c[mi][ni][3] + bias2[ni].y);
            *(float2*)(r0 + col0 + ni * 8) = v0;
            *(float2*)(r1 + col0 + ni * 8) = v1;
        }
    }
}

// ---------------------------------------------------------------------------
// bf16 mma GEMM (m16n8k16) for fc and ln:
//   C[m][n] = sum_k hs[m][k] * W[n][k] + bias[n],  K = 512
// Same CTA/warp tiling as the tf32 kernel; bf16 halves byte traffic and
// doubles tensor throughput per instruction. Row-major smem tiles,
// stride 20 words (32 bf16 = 16 words data + 4 pad); bank = g*20+t -> all
// 32 lanes distinct. kk in {0,1} (two k16 steps per BK=32 stage).
// ---------------------------------------------------------------------------
#define BS 20                      // tile row stride in 32-bit words
#define BTILE_W (128 * BS)         // 2560 words
#define BBUF_W (2 * BTILE_W)       // 5120 words (A tile + B tile)
#define BMM_SMEM_BYTES (2 * BBUF_W * 4)   // 40960

template <int OUTLD>
__global__ __launch_bounds__(256, 2) void gemm_bf16(
    const __nv_bfloat16* __restrict__ Wb,   // [N][512] bf16
    const float* __restrict__ bias,         // [N]
    float* __restrict__ outp)
{
    constexpr int KITERS = 16;   // 512 / 32
    extern __shared__ uint32_t smem[];
    const uint32_t sbase = smem_u32(smem);
    const int tid = threadIdx.x;
    const int w = tid >> 5;
    const int lane = tid & 31;
    const int g = lane >> 2;
    const int t = lane & 3;
    const int wm = w >> 2;     // 0..1
    const int wn = w & 3;      // 0..3
    const int by = blockIdx.y;
    const int m0 = by * 128;
    const int n0 = blockIdx.x * 128;

    // Staging: thread covers rows (tid>>2)+q*64 (q=0,1), 16B chunk tid&3
    const int srow = tid >> 2;
    const int schk = (tid & 3) * 8;    // bf16 element offset of 16B chunk
    const __nv_bfloat16* aP[2];
    const __nv_bfloat16* bP[2];
#pragma unroll
    for (int q = 0; q < 2; q++) {
        const int r = srow + q * 64;
        aP[q] = g_hs_b +
                ((size_t)((by & 1) * 128 + r) * 32 + (size_t)(by >> 1)) * HH +
                schk;
        bP[q] = Wb + (size_t)(n0 + r) * HH + schk;
    }
    const uint32_t stg = sbase + (uint32_t)srow * 80 + (uint32_t)(tid & 3) * 16;

    float c[4][4][4];
#pragma unroll
    for (int mi = 0; mi < 4; mi++)
#pragma unroll
        for (int ni = 0; ni < 4; ni++)
#pragma unroll
            for (int q = 0; q < 4; q++) c[mi][ni][q] = 0.f;

    auto ISSUE = [&](int s) {
        const uint32_t aD = stg + (s & 1) * (BBUF_W * 4);
        const uint32_t bD = aD + BTILE_W * 4;
        const int k0 = s * 32;
#pragma unroll
        for (int q = 0; q < 2; q++) {
            cp16(aD + q * (64 * 80), aP[q] + k0);
            cp16(bD + q * (64 * 80), bP[q] + k0);
        }
        CP_COMMIT();
    };

    ISSUE(0);
    for (int s = 0; s < KITERS; s++) {
        if (s + 1 < KITERS) { ISSUE(s + 1); CP_WAIT1(); }
        else                { CP_WAIT0(); }
        __syncthreads();

        const uint32_t* aC = smem + (s & 1) * BBUF_W + (wm * 64 + g) * BS + t;
        const uint32_t* bC = smem + (s & 1) * BBUF_W + BTILE_W +
                             (wn * 32 + g) * BS + t;
#pragma unroll
        for (int kk = 0; kk < 2; kk++) {
            uint32_t af[4][4];
#pragma unroll
            for (int mi = 0; mi < 4; mi++) {
                const uint32_t* p = aC + mi * (16 * BS) + kk * 8;
                af[mi][0] = p[0];           // (row g,    k words t)
                af[mi][1] = p[8 * BS];      // (row g+8,  k words t)
                af[mi][2] = p[4];           // (row g,    k words t+4)
                af[mi][3] = p[8 * BS + 4];  // (row g+8,  k words t+4)
            }
            uint32_t bf[4][2];
#pragma unroll
            for (int ni = 0; ni < 4; ni++) {
                const uint32_t* p = bC + ni * (8 * BS) + kk * 8;
                bf[ni][0] = p[0];
                bf[ni][1] = p[4];
            }
#pragma unroll
            for (int mi = 0; mi < 4; mi++)
#pragma unroll
                for (int ni = 0; ni < 4; ni++)
                    mma_bf16(c[mi][ni], af[mi], bf[ni]);
        }
        __syncthreads();
    }

    // Epilogue: direct STG.64 with bias
    const int col0 = n0 + wn * 32 + 2 * t;
    float2 bias2[4];
#pragma unroll
    for (int ni = 0; ni < 4; ni++)
        bias2[ni] = *(const float2*)(bias + col0 + ni * 8);
#pragma unroll
    for (int mi = 0; mi < 4; mi++) {
        int gm = m0 + wm * 64 + mi * 16 + g;
        float* r0 = outp + (size_t)gm * OUTLD;
        float* r1 = outp + (size_t)(gm + 8) * OUTLD;
#pragma unroll
        for (int ni = 0; ni < 4; ni++) {
            float2 v0 = make_float2(c[mi][ni][0] + bias2[ni].x,
                                    c[mi][ni][1] + bias2[ni].y);
            float2 v1 = make_float2(c[mi][ni][2] + bias2[ni].x,
                                    c[mi][ni][3] + bias2[ni].y);
            *(float2*)(r0 + col0 + ni * 8) = v0;
            *(float2*)(r1 + col0 + ni * 8) = v1;
        }
    }
}

// ---------------------------------------------------------------------------
// Persistent LSTM kernel (R9/R10 version: FFMA2 + conflict-free reduce).
// 128 blocks x 256 threads, 1/SM. Emits fp32 hs + bf16 hs copy.
// ---------------------------------------------------------------------------
#define LSTM_BLOCKS 128
#define LSTM_SMEM_FLOATS (32 * 512 + 16 * 513 + 512 + 128 + 16)
#define LSTM_SMEM_BYTES (LSTM_SMEM_FLOATS * 4)   // 100992

__device__ __forceinline__ int lstm_grow(int j0, int r) {
    return (r >> 2) * 512 + j0 + (r & 3);   // gate g = r>>2, unit u = r&3
}

__device__ __forceinline__ void grid_barrier() {
    __threadfence();
    __syncthreads();
    if (threadIdx.x == 0) {
        unsigned gen = g_bar_gen;
        unsigned arr = atomicAdd(&g_bar_count, 1u);
        if (arr == gridDim.x - 1) {
            g_bar_count = 0;
            __threadfence();
            g_bar_gen = gen + 1;
        } else {
            while (g_bar_gen == gen) { }
        }
    }
    __syncthreads();
    __threadfence();
}

__global__ __launch_bounds__(256) void lstm_kernel(const float* __restrict__ w_hh,
                                                   const float* __restrict__ b_hh) {
    extern __shared__ float sm[];
    float* sH    = sm;                       // [32][512]
    float* sRedT = sH + 32 * 512;            // [16 ks][513]
    float* sGate = sRedT + 16 * 513;         // [16 rows][32 b]
    float* sC    = sGate + 512;              // [4 units][32 b]
    float* sBh   = sC + 128;                 // [16]

    const int tid = threadIdx.x;
    const int bid = blockIdx.x;
    const int j0 = bid * 4;
    const int ks = tid & 15;
    const int rg = (tid >> 4) & 3;
    const int bg = tid >> 6;

    float wv[4][32];
#pragma unroll
    for (int j = 0; j < 4; j++) {
        const float* p = w_hh + (size_t)lstm_grow(j0, rg * 4 + j) * 512 + ks;
#pragma unroll
        for (int i = 0; i < 32; i++) wv[j][i] = p[i * 16];
    }
    if (tid < 16) sBh[tid] = b_hh[lstm_grow(j0, tid)];
    if (tid < 128) sC[tid] = 0.f;
    for (int i = tid; i < 32 * 512; i += 256) sH[i] = 0.f;
    __syncthreads();

    for (int t = 0; t < TT; t++) {
        if (t > 0) {
            const float4* src = (const float4*)(g_hs + (size_t)(t - 1) * 32 * 512);
            float4* dst = (float4*)sH;
#pragma unroll
            for (int i = 0; i < 16; i++) dst[tid + 256 * i] = src[tid + 256 * i];
            __syncthreads();
        }

        unsigned long long acc2[4][4];
#pragma unroll
        for (int j = 0; j < 4; j++)
#pragma unroll
            for (int p = 0; p < 4; p++) acc2[j][p] = 0ull;

        const float* hB = sH + bg * 8 * 512;
#pragma unroll
        for (int i = 0; i < 32; i++) {
            const float* hp = hB + ks + 16 * i;
            unsigned long long hp2[4];
#pragma unroll
            for (int p = 0; p < 4; p++)
                hp2[p] = pk2(hp[(2 * p) * 512], hp[(2 * p + 1) * 512]);
#pragma unroll
            for (int j = 0; j < 4; j++) {
                unsigned long long w2 = pk2(wv[j][i], wv[j][i]);
#pragma unroll
                for (int p = 0; p < 4; p++) fma2(acc2[j][p], w2, hp2[p]);
            }
        }
#pragma unroll
        for (int j = 0; j < 4; j++) {
            int r = rg * 4 + j;
#pragma unroll
            for (int p = 0; p < 4; p++) {
                float a0, a1;
                upk2(acc2[j][p], a0, a1);
                int o = r * 32 + bg * 8 + 2 * p;
                sRedT[ks * 513 + o]     = a0;
                sRedT[ks * 513 + o + 1] = a1;
            }
        }
        __syncthreads();

#pragma unroll
        for (int o2 = 0; o2 < 2; o2++) {
            int o = tid * 2 + o2;
            int r = o >> 5, b = o & 31;
            float s = 0.f;
#pragma unroll
            for (int j = 0; j < 16; j++) s += sRedT[j * 513 + o];
            s += g_xg[(size_t)(t * 32 + b) * G4 + lstm_grow(j0, r)] + sBh[r];
            sGate[o] = s;
        }
        __syncthreads();

        if (tid < 128) {
            int u = tid & 3, b = tid >> 2;
            float gi = sGate[(0 + u) * 32 + b];
            float gf = sGate[(4 + u) * 32 + b];
            float gg = sGate[(8 + u) * 32 + b];
            float go = sGate[(12 + u) * 32 + b];
            float cc = sC[u * 32 + b];
            float si = 1.f / (1.f + expf(-gi));
            float sf = 1.f / (1.f + expf(-gf));
            float so = 1.f / (1.f + expf(-go));
            cc = sf * cc + si * tanhf(gg);
            float h = so * tanhf(cc);
            sC[u * 32 + b] = cc;
            size_t off = (size_t)(t * 32 + b) * 512 + j0 + u;
            g_hs[off] = h;
            g_hs_b[off] = __float2bfloat16(h);
        }
        grid_barrier();
    }
}

// ---------------------------------------------------------------------------
// Launch
// ---------------------------------------------------------------------------
extern "C" void kernel_launch(void* const* d_in, const int* in_sizes, int n_in,
                              void* d_out, int out_size) {
    const void*  x       = d_in[0];
    const float* embed_w = (const float*)d_in[1];
    const float* w_ih    = (const float*)d_in[2];
    const float* w_hh    = (const float*)d_in[3];
    const float* b_ih    = (const float*)d_in[4];
    const float* b_hh    = (const float*)d_in[5];
    const float* fc_w    = (const float*)d_in[6];
    const float* fc_b    = (const float*)d_in[7];
    const float* ln_w    = (const float*)d_in[8];
    const float* ln_b    = (const float*)d_in[9];

    float* out    = (float*)d_out;
    float* states = out + (size_t)BT * VV;

    float *emb_t, *wih_t;
    __nv_bfloat16 *fcw_b, *lnw_b;
    cudaGetSymbolAddress((void**)&emb_t, g_emb_t);
    cudaGetSymbolAddress((void**)&wih_t, g_wih_t);
    cudaGetSymbolAddress((void**)&fcw_b, g_fcw_b);
    cudaGetSymbolAddress((void**)&lnw_b, g_lnw_b);

    // 1) decode token indices
    decode_idx_kernel<<<BT / 256, 256>>>(x);

    // 2) pre-round weights: tf32 for xg path, bf16 for fc/ln
    cvt_tf32_kernel<<<(VV * EE / 4) / 256, 256>>>(emb_t, embed_w, VV * EE / 4);
    cvt_tf32_kernel<<<(G4 * EE / 4) / 256, 256>>>(wih_t, w_ih, G4 * EE / 4);
    cvt_bf16_kernel<<<(VV * HH / 8) / 256, 256>>>(fcw_b, fc_w, VV * HH / 8);
    cvt_bf16_kernel<<<(HH * HH / 8) / 256, 256>>>(lnw_b, ln_w, HH * HH / 8);

    // 3) xg = embed[x] @ w_ih^T + b_ih   (tensor tf32, K=256)
    cudaFuncSetAttribute(gemm_xg_mma,
                         cudaFuncAttributeMaxDynamicSharedMemorySize, MM_SMEM_BYTES);
    gemm_xg_mma<<<dim3(G4 / 128, BT / 128), 256, MM_SMEM_BYTES>>>(wih_t, b_ih);

    // 4) sequential LSTM (fp32 recurrence; emits fp32 + bf16 hs)
    cudaFuncSetAttribute(lstm_kernel, cudaFuncAttributeMaxDynamicSharedMemorySize,
                         LSTM_SMEM_BYTES);
    lstm_kernel<<<LSTM_BLOCKS, 256, LSTM_SMEM_BYTES>>>(w_hh, b_hh);

    // 5) out = hs @ fc_w^T + fc_b   (tensor bf16, K=512)
    cudaFuncSetAttribute(gemm_bf16<VV>,
                         cudaFuncAttributeMaxDynamicSharedMemorySize, BMM_SMEM_BYTES);
    gemm_bf16<VV><<<dim3(VV / 128, BT / 128), 256, BMM_SMEM_BYTES>>>(
        fcw_b, fc_b, out);

    // 6) states = hs @ ln_w^T + ln_b   (tensor bf16, K=512)
    cudaFuncSetAttribute(gemm_bf16<HH>,
                         cudaFuncAttributeMaxDynamicSharedMemorySize, BMM_SMEM_BYTES);
    gemm_bf16<HH><<<dim3(HH / 128, BT / 128), 256, BMM_SMEM_BYTES>>>(
        lnw_b, ln_b, states);
}

// round 12
// speedup vs baseline: 1.7091x; 1.0092x over previous
#include <cuda_runtime.h>
#include <cuda_fp16.h>
#include <math.h>
#include <stdint.h>

// Problem constants
#define BB 32
#define TT 256
#define EE 256
#define HH 512
#define G4 2048          // 4*H
#define VV 32000
#define BT 8192          // B*T

// ---------------------------------------------------------------------------
// Scratch (no allocations allowed -> __device__ globals)
// ---------------------------------------------------------------------------
__device__ int g_idx[BT];
__device__ float g_xg[(size_t)BT * G4];     // [t][b][4H] gate preactivations
__device__ float g_hs[(size_t)BT * HH];     // [t][b][H] hidden states (fp32)
__device__ __half g_hs_h[(size_t)BT * HH];  // fp16 copy for fc/ln GEMMs
__device__ __half g_emb_h[(size_t)VV * EE]; // fp16 embed_w
__device__ __half g_wih_h[(size_t)G4 * EE]; // fp16 w_ih
__device__ __half g_fcw_h[(size_t)VV * HH]; // fp16 fc_w
__device__ __half g_lnw_h[(size_t)HH * HH]; // fp16 ln_w
__device__ unsigned g_bar_count = 0;
__device__ volatile unsigned g_bar_gen = 0;

// ---------------------------------------------------------------------------
// Small helpers
// ---------------------------------------------------------------------------
__device__ __forceinline__ uint32_t f16x2(float lo, float hi) {
    uint32_t r;
    asm("cvt.rn.f16x2.f32 %0, %1, %2;" : "=r"(r) : "f"(hi), "f"(lo));
    return r;
}
__device__ __forceinline__ unsigned long long pk2(float x, float y) {
    unsigned long long r;
    asm("mov.b64 %0, {%1, %2};" : "=l"(r) : "f"(x), "f"(y));
    return r;
}
__device__ __forceinline__ void upk2(unsigned long long v, float& x, float& y) {
    asm("mov.b64 {%0, %1}, %2;" : "=f"(x), "=f"(y) : "l"(v));
}
__device__ __forceinline__ void fma2(unsigned long long& d, unsigned long long a,
                                     unsigned long long b) {
    asm("fma.rn.f32x2 %0, %1, %2, %3;" : "=l"(d) : "l"(a), "l"(b), "l"(d));
}
__device__ __forceinline__ uint32_t smem_u32(const void* p) {
    uint32_t a;
    asm("{ .reg .u64 t; cvta.to.shared.u64 t, %1; cvt.u32.u64 %0, t; }"
        : "=r"(a) : "l"(p));
    return a;
}
__device__ __forceinline__ void cp16(uint32_t dst, const void* src) {
    asm volatile("cp.async.cg.shared.global [%0], [%1], 16;"
                 :: "r"(dst), "l"(src) : "memory");
}
#define CP_COMMIT() asm volatile("cp.async.commit_group;" ::: "memory")
#define CP_WAIT1()  asm volatile("cp.async.wait_group 1;" ::: "memory")
#define CP_WAIT0()  asm volatile("cp.async.wait_group 0;" ::: "memory")

__device__ __forceinline__ void mma_f16(float* c, const uint32_t* a,
                                        const uint32_t* b) {
    asm volatile(
        "mma.sync.aligned.m16n8k16.row.col.f32.f16.f16.f32 "
        "{%0,%1,%2,%3}, {%4,%5,%6,%7}, {%8,%9}, {%0,%1,%2,%3};"
        : "+f"(c[0]), "+f"(c[1]), "+f"(c[2]), "+f"(c[3])
        : "r"(a[0]), "r"(a[1]), "r"(a[2]), "r"(a[3]), "r"(b[0]), "r"(b[1]));
}

// ---------------------------------------------------------------------------
// Token index decode: handles both int64 and int32 storage of x
// ---------------------------------------------------------------------------
__global__ void decode_idx_kernel(const void* __restrict__ xin) {
    int i = blockIdx.x * blockDim.x + threadIdx.x;
    if (i >= BT) return;
    const long long* x64 = (const long long*)xin;
    bool is64 = true;
#pragma unroll
    for (int j = 0; j < 8; j++) {
        long long v = x64[j];
        if (v < 0 || v >= VV) is64 = false;
    }
    g_idx[i] = is64 ? (int)x64[i] : ((const int*)xin)[i];
}

// ---------------------------------------------------------------------------
// Convert fp32 -> fp16 (RN), 8 elements per thread, 16B reads/8B writes.
// ---------------------------------------------------------------------------
__global__ void cvt_f16_kernel(__half* __restrict__ dst,
                               const float* __restrict__ src, int n8) {
    int i = blockIdx.x * blockDim.x + threadIdx.x;
    if (i >= n8) return;
    float4 v0 = ((const float4*)src)[2 * i];
    float4 v1 = ((const float4*)src)[2 * i + 1];
    uint4 o = make_uint4(f16x2(v0.x, v0.y), f16x2(v0.z, v0.w),
                         f16x2(v1.x, v1.y), f16x2(v1.z, v1.w));
    ((uint4*)dst)[i] = o;
}

// ---------------------------------------------------------------------------
// fp16 mma GEMM (m16n8k16) — unified for xg / fc / ln:
//   C[m][n] = sum_k A[m][k] * W[n][k] + bias[n]
// CTA 128x128, BK=32, 256 threads, 8 warps (2M x 4N), warp tile 64x32.
// Row-major smem tiles, stride 20 words (16 data + 4 pad); bank = g*20+t
// -> all 32 lanes distinct, conflict-free. cp.async.cg staging, 2 stages.
//   MODE 0: fc (A=g_hs_h remap, K=512, out stride VV)
//   MODE 1: ln (A=g_hs_h remap, K=512, out stride HH)
//   MODE 2: xg (A=g_emb_h gathered via g_idx, K=256, out -> g_xg remap)
// ---------------------------------------------------------------------------
#define BS 20                      // tile row stride in 32-bit words
#define BTILE_W (128 * BS)         // 2560 words
#define BBUF_W (2 * BTILE_W)       // 5120 words (A tile + B tile)
#define BMM_SMEM_BYTES (2 * BBUF_W * 4)   // 40960

template <int KITERS, int MODE>
__global__ __launch_bounds__(256, 2) void gemm_f16(
    const __half* __restrict__ Wh,   // [N][K] fp16
    const float* __restrict__ bias,  // [N]
    float* __restrict__ outp)
{
    constexpr int K = KITERS * 32;
    extern __shared__ uint32_t smem[];
    const uint32_t sbase = smem_u32(smem);
    const int tid = threadIdx.x;
    const int w = tid >> 5;
    const int lane = tid & 31;
    const int g = lane >> 2;
    const int t = lane & 3;
    const int wm = w >> 2;     // 0..1
    const int wn = w & 3;      // 0..3
    const int by = blockIdx.y;
    const int m0 = by * 128;
    const int n0 = blockIdx.x * 128;

    // Staging: thread covers rows (tid>>2)+q*64 (q=0,1), 16B chunk tid&3
    const int srow = tid >> 2;
    const int schk = (tid & 3) * 8;    // fp16 element offset of 16B chunk
    const __half* aP[2];
    const __half* bP[2];
#pragma unroll
    for (int q = 0; q < 2; q++) {
        const int r = srow + q * 64;
        if (MODE == 2) {
            aP[q] = g_emb_h + (size_t)g_idx[m0 + r] * EE + schk;
        } else {
            aP[q] = g_hs_h +
                    ((size_t)((by & 1) * 128 + r) * 32 + (size_t)(by >> 1)) * HH +
                    schk;
        }
        bP[q] = Wh + (size_t)(n0 + r) * K + schk;
    }
    const uint32_t stg = sbase + (uint32_t)srow * 80 + (uint32_t)(tid & 3) * 16;

    float c[4][4][4];
#pragma unroll
    for (int mi = 0; mi < 4; mi++)
#pragma unroll
        for (int ni = 0; ni < 4; ni++)
#pragma unroll
            for (int q = 0; q < 4; q++) c[mi][ni][q] = 0.f;

    auto ISSUE = [&](int s) {
        const uint32_t aD = stg + (s & 1) * (BBUF_W * 4);
        const uint32_t bD = aD + BTILE_W * 4;
        const int k0 = s * 32;
#pragma unroll
        for (int q = 0; q < 2; q++) {
            cp16(aD + q * (64 * 80), aP[q] + k0);
            cp16(bD + q * (64 * 80), bP[q] + k0);
        }
        CP_COMMIT();
    };

    ISSUE(0);
    for (int s = 0; s < KITERS; s++) {
        if (s + 1 < KITERS) { ISSUE(s + 1); CP_WAIT1(); }
        else                { CP_WAIT0(); }
        __syncthreads();

        const uint32_t* aC = smem + (s & 1) * BBUF_W + (wm * 64 + g) * BS + t;
        const uint32_t* bC = smem + (s & 1) * BBUF_W + BTILE_W +
                             (wn * 32 + g) * BS + t;
#pragma unroll
        for (int kk = 0; kk < 2; kk++) {
            uint32_t af[4][4];
#pragma unroll
            for (int mi = 0; mi < 4; mi++) {
                const uint32_t* p = aC + mi * (16 * BS) + kk * 8;
                af[mi][0] = p[0];           // (row g,    k elems 2t..2t+1)
                af[mi][1] = p[8 * BS];      // (row g+8)
                af[mi][2] = p[4];           // (row g,    k elems 2t+8..)
                af[mi][3] = p[8 * BS + 4];  // (row g+8)
            }
            uint32_t bf[4][2];
#pragma unroll
            for (int ni = 0; ni < 4; ni++) {
                const uint32_t* p = bC + ni * (8 * BS) + kk * 8;
                bf[ni][0] = p[0];
                bf[ni][1] = p[4];
            }
#pragma unroll
            for (int mi = 0; mi < 4; mi++)
#pragma unroll
                for (int ni = 0; ni < 4; ni++)
                    mma_f16(c[mi][ni], af[mi], bf[ni]);
        }
        __syncthreads();
    }

    // Epilogue: direct STG.64 with bias
    const int col0 = n0 + wn * 32 + 2 * t;
    float2 bias2[4];
#pragma unroll
    for (int ni = 0; ni < 4; ni++)
        bias2[ni] = *(const float2*)(bias + col0 + ni * 8);
#pragma unroll
    for (int mi = 0; mi < 4; mi++) {
        int gm = m0 + wm * 64 + mi * 16 + g;
        float *r0, *r1;
        if (MODE == 0) {
            r0 = outp + (size_t)gm * VV;
            r1 = outp + (size_t)(gm + 8) * VV;
        } else if (MODE == 1) {
            r0 = outp + (size_t)gm * HH;
            r1 = outp + (size_t)(gm + 8) * HH;
        } else {
            int gm8 = gm + 8;
            r0 = g_xg + (size_t)((gm & 255) * 32 + (gm >> 8)) * G4;
            r1 = g_xg + (size_t)((gm8 & 255) * 32 + (gm8 >> 8)) * G4;
        }
#pragma unroll
        for (int ni = 0; ni < 4; ni++) {
            float2 v0 = make_float2(c[mi][ni][0] + bias2[ni].x,
                                    c[mi][ni][1] + bias2[ni].y);
            float2 v1 = make_float2(c[mi][ni][2] + bias2[ni].x,
                                    c[mi][ni][3] + bias2[ni].y);
            *(float2*)(r0 + col0 + ni * 8) = v0;
            *(float2*)(r1 + col0 + ni * 8) = v1;
        }
    }
}

// ---------------------------------------------------------------------------
// Persistent LSTM kernel (proven: FFMA2 + conflict-free reduce).
// 128 blocks x 256 threads, 1/SM. Emits fp32 hs + fp16 hs copy.
// ---------------------------------------------------------------------------
#define LSTM_BLOCKS 128
#define LSTM_SMEM_FLOATS (32 * 512 + 16 * 513 + 512 + 128 + 16)
#define LSTM_SMEM_BYTES (LSTM_SMEM_FLOATS * 4)   // 100992

__device__ __forceinline__ int lstm_grow(int j0, int r) {
    return (r >> 2) * 512 + j0 + (r & 3);   // gate g = r>>2, unit u = r&3
}

__device__ __forceinline__ void grid_barrier() {
    __threadfence();
    __syncthreads();
    if (threadIdx.x == 0) {
        unsigned gen = g_bar_gen;
        unsigned arr = atomicAdd(&g_bar_count, 1u);
        if (arr == gridDim.x - 1) {
            g_bar_count = 0;
            __threadfence();
            g_bar_gen = gen + 1;
        } else {
            while (g_bar_gen == gen) { }
        }
    }
    __syncthreads();
    __threadfence();
}

__global__ __launch_bounds__(256) void lstm_kernel(const float* __restrict__ w_hh,
                                                   const float* __restrict__ b_hh) {
    extern __shared__ float sm[];
    float* sH    = sm;                       // [32][512]
    float* sRedT = sH + 32 * 512;            // [16 ks][513]
    float* sGate = sRedT + 16 * 513;         // [16 rows][32 b]
    float* sC    = sGate + 512;              // [4 units][32 b]
    float* sBh   = sC + 128;                 // [16]

    const int tid = threadIdx.x;
    const int bid = blockIdx.x;
    const int j0 = bid * 4;
    const int ks = tid & 15;
    const int rg = (tid >> 4) & 3;
    const int bg = tid >> 6;

    float wv[4][32];
#pragma unroll
    for (int j = 0; j < 4; j++) {
        const float* p = w_hh + (size_t)lstm_grow(j0, rg * 4 + j) * 512 + ks;
#pragma unroll
        for (int i = 0; i < 32; i++) wv[j][i] = p[i * 16];
    }
    if (tid < 16) sBh[tid] = b_hh[lstm_grow(j0, tid)];
    if (tid < 128) sC[tid] = 0.f;
    for (int i = tid; i < 32 * 512; i += 256) sH[i] = 0.f;
    __syncthreads();

    for (int t = 0; t < TT; t++) {
        if (t > 0) {
            const float4* src = (const float4*)(g_hs + (size_t)(t - 1) * 32 * 512);
            float4* dst = (float4*)sH;
#pragma unroll
            for (int i = 0; i < 16; i++) dst[tid + 256 * i] = src[tid + 256 * i];
            __syncthreads();
        }

        unsigned long long acc2[4][4];
#pragma unroll
        for (int j = 0; j < 4; j++)
#pragma unroll
            for (int p = 0; p < 4; p++) acc2[j][p] = 0ull;

        const float* hB = sH + bg * 8 * 512;
#pragma unroll
        for (int i = 0; i < 32; i++) {
            const float* hp = hB + ks + 16 * i;
            unsigned long long hp2[4];
#pragma unroll
            for (int p = 0; p < 4; p++)
                hp2[p] = pk2(hp[(2 * p) * 512], hp[(2 * p + 1) * 512]);
#pragma unroll
            for (int j = 0; j < 4; j++) {
                unsigned long long w2 = pk2(wv[j][i], wv[j][i]);
#pragma unroll
                for (int p = 0; p < 4; p++) fma2(acc2[j][p], w2, hp2[p]);
            }
        }
#pragma unroll
        for (int j = 0; j < 4; j++) {
            int r = rg * 4 + j;
#pragma unroll
            for (int p = 0; p < 4; p++) {
                float a0, a1;
                upk2(acc2[j][p], a0, a1);
                int o = r * 32 + bg * 8 + 2 * p;
                sRedT[ks * 513 + o]     = a0;
                sRedT[ks * 513 + o + 1] = a1;
            }
        }
        __syncthreads();

#pragma unroll
        for (int o2 = 0; o2 < 2; o2++) {
            int o = tid * 2 + o2;
            int r = o >> 5, b = o & 31;
            float s = 0.f;
#pragma unroll
            for (int j = 0; j < 16; j++) s += sRedT[j * 513 + o];
            s += g_xg[(size_t)(t * 32 + b) * G4 + lstm_grow(j0, r)] + sBh[r];
            sGate[o] = s;
        }
        __syncthreads();

        if (tid < 128) {
            int u = tid & 3, b = tid >> 2;
            float gi = sGate[(0 + u) * 32 + b];
            float gf = sGate[(4 + u) * 32 + b];
            float gg = sGate[(8 + u) * 32 + b];
            float go = sGate[(12 + u) * 32 + b];
            float cc = sC[u * 32 + b];
            float si = 1.f / (1.f + expf(-gi));
            float sf = 1.f / (1.f + expf(-gf));
            float so = 1.f / (1.f + expf(-go));
            cc = sf * cc + si * tanhf(gg);
            float h = so * tanhf(cc);
            sC[u * 32 + b] = cc;
            size_t off = (size_t)(t * 32 + b) * 512 + j0 + u;
            g_hs[off] = h;
            g_hs_h[off] = __float2half(h);
        }
        grid_barrier();
    }
}

// ---------------------------------------------------------------------------
// Launch
// ---------------------------------------------------------------------------
extern "C" void kernel_launch(void* const* d_in, const int* in_sizes, int n_in,
                              void* d_out, int out_size) {
    const void*  x       = d_in[0];
    const float* embed_w = (const float*)d_in[1];
    const float* w_ih    = (const float*)d_in[2];
    const float* w_hh    = (const float*)d_in[3];
    const float* b_ih    = (const float*)d_in[4];
    const float* b_hh    = (const float*)d_in[5];
    const float* fc_w    = (const float*)d_in[6];
    const float* fc_b    = (const float*)d_in[7];
    const float* ln_w    = (const float*)d_in[8];
    const float* ln_b    = (const float*)d_in[9];

    float* out    = (float*)d_out;
    float* states = out + (size_t)BT * VV;

    __half *emb_h, *wih_h, *fcw_h, *lnw_h;
    cudaGetSymbolAddress((void**)&emb_h, g_emb_h);
    cudaGetSymbolAddress((void**)&wih_h, g_wih_h);
    cudaGetSymbolAddress((void**)&fcw_h, g_fcw_h);
    cudaGetSymbolAddress((void**)&lnw_h, g_lnw_h);

    // 1) decode token indices
    decode_idx_kernel<<<BT / 256, 256>>>(x);

    // 2) pre-convert all GEMM operands to fp16 (RN)
    cvt_f16_kernel<<<(VV * EE / 8) / 256, 256>>>(emb_h, embed_w, VV * EE / 8);
    cvt_f16_kernel<<<(G4 * EE / 8) / 256, 256>>>(wih_h, w_ih, G4 * EE / 8);
    cvt_f16_kernel<<<(VV * HH / 8) / 256, 256>>>(fcw_h, fc_w, VV * HH / 8);
    cvt_f16_kernel<<<(HH * HH / 8) / 256, 256>>>(lnw_h, ln_w, HH * HH / 8);

    // 3) xg = embed[x] @ w_ih^T + b_ih   (tensor fp16, K=256)
    cudaFuncSetAttribute(gemm_f16<8, 2>,
                         cudaFuncAttributeMaxDynamicSharedMemorySize, BMM_SMEM_BYTES);
    gemm_f16<8, 2><<<dim3(G4 / 128, BT / 128), 256, BMM_SMEM_BYTES>>>(
        wih_h, b_ih, nullptr);

    // 4) sequential LSTM (fp32 recurrence; emits fp32 + fp16 hs)
    cudaFuncSetAttribute(lstm_kernel, cudaFuncAttributeMaxDynamicSharedMemorySize,
                         LSTM_SMEM_BYTES);
    lstm_kernel<<<LSTM_BLOCKS, 256, LSTM_SMEM_BYTES>>>(w_hh, b_hh);

    // 5) out = hs @ fc_w^T + fc_b   (tensor fp16, K=512)
    cudaFuncSetAttribute(gemm_f16<16, 0>,
                         cudaFuncAttributeMaxDynamicSharedMemorySize, BMM_SMEM_BYTES);
    gemm_f16<16, 0><<<dim3(VV / 128, BT / 128), 256, BMM_SMEM_BYTES>>>(
        fcw_h, fc_b, out);

    // 6) states = hs @ ln_w^T + ln_b   (tensor fp16, K=512)
    cudaFuncSetAttribute(gemm_f16<16, 1>,
                         cudaFuncAttributeMaxDynamicSharedMemorySize, BMM_SMEM_BYTES);
    gemm_f16<16, 1><<<dim3(HH / 128, BT / 128), 256, BMM_SMEM_BYTES>>>(
        lnw_h, ln_b, states);
}